// round 11
// baseline (speedup 1.0000x reference)
#include <cuda_runtime.h>
#include <math.h>
#include <stdint.h>

#define N_NODES   50000
#define N_EDGES   800000
#define NF        96
#define NH        128
#define NC        40
#define GROWS     32                    // rows per GEMM block
#define SCAN_B    1024
#define NB1       ((N_NODES + SCAN_B - 1) / SCAN_B)   // 49

// ---------------- device scratch (static, allocation-free) ----------------
// Symbols referenced ONLY from device code (host-side use gives shadow addr).
__device__ __align__(16) float g_t   [N_NODES * NC];  // norm*feat@M2^T, prop state
__device__ __align__(16) float g_acc [N_NODES * NC];  // hop-1 result
__device__ float g_norm[N_NODES];
__device__ int   g_deg  [N_NODES];
__device__ int   g_off  [N_NODES];
__device__ int   g_cursor[N_NODES];
__device__ int   g_bsum [NB1];
__device__ int   g_bcarry[NB1];
__device__ int   g_csr  [N_EDGES];                    // src ids grouped by dst
__device__ float g_M1p[4 * NF * NC];                  // K-split partials, [f][c]
__device__ float g_M2p[4 * NF * NC];

// ---------------------------------------------------------------------------
__global__ void k_init() {
    int i = blockIdx.x * blockDim.x + threadIdx.x;
    if (i < N_NODES) g_deg[i] = 0;
}

__global__ void k_deg(const int* __restrict__ dst) {
    int e = blockIdx.x * blockDim.x + threadIdx.x;
    if (e < N_EDGES) atomicAdd(&g_deg[dst[e]], 1);
}

// Two-level exclusive scan of g_deg -> g_off
__global__ void k_scan1() {
    __shared__ int sh[SCAN_B];
    int i = blockIdx.x * SCAN_B + threadIdx.x;
    int v = (i < N_NODES) ? g_deg[i] : 0;
    sh[threadIdx.x] = v;
    __syncthreads();
    for (int off = 1; off < SCAN_B; off <<= 1) {
        int t = (threadIdx.x >= off) ? sh[threadIdx.x - off] : 0;
        __syncthreads();
        sh[threadIdx.x] += t;
        __syncthreads();
    }
    if (i < N_NODES) g_off[i] = sh[threadIdx.x] - v;      // exclusive, block-local
    if (threadIdx.x == SCAN_B - 1) g_bsum[blockIdx.x] = sh[SCAN_B - 1];
}

__global__ void k_scan2() {
    if (threadIdx.x == 0) {
        int run = 0;
        for (int b = 0; b < NB1; b++) { g_bcarry[b] = run; run += g_bsum[b]; }
    }
}

// finalize offsets + cursors + norms
__global__ void k_scan3() {
    int i = blockIdx.x * blockDim.x + threadIdx.x;
    if (i >= N_NODES) return;
    int off = g_off[i] + g_bcarry[i >> 10];
    g_off[i] = off;
    g_cursor[i] = off;
    int d = g_deg[i];
    g_norm[i] = (d > 0) ? rsqrtf((float)d) : 1.0f;
}

__global__ void k_fill(const int* __restrict__ src, const int* __restrict__ dst) {
    int e = blockIdx.x * blockDim.x + threadIdx.x;
    if (e >= N_EDGES) return;
    int d = dst[e];
    int pos = atomicAdd(&g_cursor[d], 1);
    g_csr[pos] = src[e];
}

// Folded projection weights, K-split 4x for latency hiding.
// M1[c,f] = sum_h Wp[c,h]     * W_lin[h,f]
// M2[c,f] = sum_h Wp[c,128+h] * W_sgc[h,f]
__global__ void k_weights(const float* __restrict__ Wp,
                          const float* __restrict__ Wsgc,
                          const float* __restrict__ Wlin) {
    int c    = blockIdx.x;        // 0..39
    int sel  = blockIdx.y;        // 0 -> M1, 1 -> M2
    int part = blockIdx.z;        // 0..3, 32 h each
    int f    = threadIdx.x;       // 0..95
    const float* wp = Wp + c * 256 + sel * 128 + part * 32;
    const float* W  = (sel ? Wsgc : Wlin) + part * 32 * NF;
    float acc = 0.0f;
#pragma unroll
    for (int h = 0; h < 32; h++)
        acc = fmaf(__ldg(wp + h), __ldg(W + h * NF + f), acc);
    (sel ? g_M2p : g_M1p)[part * (NF * NC) + f * NC + c] = acc;
}

__device__ __forceinline__ void fma4(float4& a, float s, const float4 m) {
    a.x = fmaf(s, m.x, a.x);
    a.y = fmaf(s, m.y, a.y);
    a.z = fmaf(s, m.z, a.z);
    a.w = fmaf(s, m.w, a.w);
}
__device__ __forceinline__ void add4(float4& a, const float4 b) {
    a.x += b.x; a.y += b.y; a.z += b.z; a.w += b.w;
}

// Fused dual GEMM:
//   out[v,:] = feat[v,:] @ M1^T            (base term, straight to d_out)
//   g_t[v,:] = norm[v] * (feat[v,:]@M2^T)  (pre-scaled propagation input)
__global__ void __launch_bounds__(160) k_gemm(const float* __restrict__ feat,
                                              float* __restrict__ out) {
    __shared__ __align__(16) float sF [GROWS * 97];
    __shared__ __align__(16) float sM1[NF * NC];
    __shared__ __align__(16) float sM2[NF * NC];

    const int tid = threadIdx.y * 10 + threadIdx.x;
    for (int i = tid; i < NF * NC; i += 160) {
        sM1[i] = g_M1p[i] + g_M1p[i + 3840] + g_M1p[i + 7680] + g_M1p[i + 11520];
        sM2[i] = g_M2p[i] + g_M2p[i + 3840] + g_M2p[i + 7680] + g_M2p[i + 11520];
    }

    const int row0 = blockIdx.x * GROWS;
    for (int i = tid; i < GROWS * NF; i += 160) {
        int r = i / NF, f = i - r * NF;
        int v = row0 + r;
        sF[r * 97 + f] = (v < N_NODES) ? feat[(size_t)v * NF + f] : 0.0f;
    }
    __syncthreads();

    const int cx = threadIdx.x;
    const int r0 = threadIdx.y * 2;

    float4 a1r0 = make_float4(0, 0, 0, 0), a1r1 = a1r0;
    float4 a2r0 = a1r0, a2r1 = a1r0;

#pragma unroll 8
    for (int f = 0; f < NF; f++) {
        const float4 m1 = *reinterpret_cast<const float4*>(sM1 + f * NC + cx * 4);
        const float4 m2 = *reinterpret_cast<const float4*>(sM2 + f * NC + cx * 4);
        const float f0 = sF[r0 * 97 + f];
        const float f1 = sF[(r0 + 1) * 97 + f];
        fma4(a1r0, f0, m1); fma4(a2r0, f0, m2);
        fma4(a1r1, f1, m1); fma4(a2r1, f1, m2);
    }

    const int v0 = row0 + r0;
    if (v0 < N_NODES) {
        float n = g_norm[v0];
        *reinterpret_cast<float4*>(out + (size_t)v0 * NC + cx * 4) = a1r0;
        float4 t = a2r0; t.x *= n; t.y *= n; t.z *= n; t.w *= n;
        *reinterpret_cast<float4*>(g_t + (size_t)v0 * NC + cx * 4) = t;
    }
    const int v1 = v0 + 1;
    if (v1 < N_NODES) {
        float n = g_norm[v1];
        *reinterpret_cast<float4*>(out + (size_t)v1 * NC + cx * 4) = a1r1;
        float4 t = a2r1; t.x *= n; t.y *= n; t.z *= n; t.w *= n;
        *reinterpret_cast<float4*>(g_t + (size_t)v1 * NC + cx * 4) = t;
    }
}

// Hop 1 (CSR gather): g_acc[v,:] = n[v]^2 * sum_{s in in(v)} g_t[s,:]
// One thread per (v, half-row): 5 float4 accumulators. No atomics, no zeroing.
__global__ void k_gather1() {
    int t = blockIdx.x * blockDim.x + threadIdx.x;
    if (t >= N_NODES * 2) return;
    int v = t >> 1, h = t & 1;
    int beg = g_off[v], deg = g_deg[v];
    float4 a0 = make_float4(0, 0, 0, 0), a1 = a0, a2 = a0, a3 = a0, a4 = a0;
#pragma unroll 2
    for (int i = 0; i < deg; i++) {
        int s = __ldg(g_csr + beg + i);
        const float4* p = reinterpret_cast<const float4*>(g_t + (size_t)s * NC) + h * 5;
        add4(a0, p[0]); add4(a1, p[1]); add4(a2, p[2]); add4(a3, p[3]); add4(a4, p[4]);
    }
    float n = g_norm[v];
    float s2 = n * n;
    float4* o = reinterpret_cast<float4*>(g_acc + (size_t)v * NC) + h * 5;
    a0.x *= s2; a0.y *= s2; a0.z *= s2; a0.w *= s2; o[0] = a0;
    a1.x *= s2; a1.y *= s2; a1.z *= s2; a1.w *= s2; o[1] = a1;
    a2.x *= s2; a2.y *= s2; a2.z *= s2; a2.w *= s2; o[2] = a2;
    a3.x *= s2; a3.y *= s2; a3.z *= s2; a3.w *= s2; o[3] = a3;
    a4.x *= s2; a4.y *= s2; a4.z *= s2; a4.w *= s2; o[4] = a4;
}

// Hop 2 + epilogue: out[v,:] += n[v] * sum_{s in in(v)} g_acc[s,:]
__global__ void k_gather2(float* __restrict__ out) {
    int t = blockIdx.x * blockDim.x + threadIdx.x;
    if (t >= N_NODES * 2) return;
    int v = t >> 1, h = t & 1;
    int beg = g_off[v], deg = g_deg[v];
    float4 a0 = make_float4(0, 0, 0, 0), a1 = a0, a2 = a0, a3 = a0, a4 = a0;
#pragma unroll 2
    for (int i = 0; i < deg; i++) {
        int s = __ldg(g_csr + beg + i);
        const float4* p = reinterpret_cast<const float4*>(g_acc + (size_t)s * NC) + h * 5;
        add4(a0, p[0]); add4(a1, p[1]); add4(a2, p[2]); add4(a3, p[3]); add4(a4, p[4]);
    }
    float n = g_norm[v];
    float4* o = reinterpret_cast<float4*>(out + (size_t)v * NC) + h * 5;
    float4 b;
    b = o[0]; b.x = fmaf(n, a0.x, b.x); b.y = fmaf(n, a0.y, b.y); b.z = fmaf(n, a0.z, b.z); b.w = fmaf(n, a0.w, b.w); o[0] = b;
    b = o[1]; b.x = fmaf(n, a1.x, b.x); b.y = fmaf(n, a1.y, b.y); b.z = fmaf(n, a1.z, b.z); b.w = fmaf(n, a1.w, b.w); o[1] = b;
    b = o[2]; b.x = fmaf(n, a2.x, b.x); b.y = fmaf(n, a2.y, b.y); b.z = fmaf(n, a2.z, b.z); b.w = fmaf(n, a2.w, b.w); o[2] = b;
    b = o[3]; b.x = fmaf(n, a3.x, b.x); b.y = fmaf(n, a3.y, b.y); b.z = fmaf(n, a3.z, b.z); b.w = fmaf(n, a3.w, b.w); o[3] = b;
    b = o[4]; b.x = fmaf(n, a4.x, b.x); b.y = fmaf(n, a4.y, b.y); b.z = fmaf(n, a4.z, b.z); b.w = fmaf(n, a4.w, b.w); o[4] = b;
}

// ---------------------------------------------------------------------------
extern "C" void kernel_launch(void* const* d_in, const int* in_sizes, int n_in,
                              void* d_out, int out_size) {
    const float* feat  = (const float*)d_in[0];   // [50000, 96]
    const int*   src   = (const int*)  d_in[1];   // [800000]
    const int*   dst   = (const int*)  d_in[2];   // [800000]
    const float* Wsgc  = (const float*)d_in[3];   // [128, 96]
    const float* Wlin  = (const float*)d_in[4];   // [128, 96]
    const float* Wproj = (const float*)d_in[5];   // [40, 256]
    float* out = (float*)d_out;                   // [50000, 40]

    k_init<<<(N_NODES + 255) / 256, 256>>>();
    k_deg <<<(N_EDGES + 255) / 256, 256>>>(dst);
    k_scan1<<<NB1, SCAN_B>>>();
    k_scan2<<<1, 32>>>();
    k_scan3<<<(N_NODES + 255) / 256, 256>>>();
    k_fill<<<(N_EDGES + 255) / 256, 256>>>(src, dst);
    k_weights<<<dim3(NC, 2, 4), NF>>>(Wproj, Wsgc, Wlin);
    k_gemm<<<(N_NODES + GROWS - 1) / GROWS, dim3(10, 16)>>>(feat, out);
    k_gather1<<<(N_NODES * 2 + 255) / 256, 256>>>();
    k_gather2<<<(N_NODES * 2 + 255) / 256, 256>>>(out);
}

// round 12
// speedup vs baseline: 1.4683x; 1.4683x over previous
#include <cuda_runtime.h>
#include <math.h>
#include <stdint.h>

#define N_NODES   50000
#define N_EDGES   800000
#define NF        96
#define NH        128
#define NC        40
#define GROWS     64                    // rows per GEMM block
#define SCAN_B    1024
#define NB1       ((N_NODES + SCAN_B - 1) / SCAN_B)   // 49

// ---------------- device scratch (static, allocation-free) ----------------
// Symbols referenced ONLY from device code (host-side use gives shadow addr).
__device__ __align__(16) float g_t   [N_NODES * NC];  // norm*feat@M2^T, prop state
__device__ __align__(16) float g_acc [N_NODES * NC];  // hop-1 result
__device__ float g_norm[N_NODES];
__device__ int   g_deg  [N_NODES];
__device__ int   g_off  [N_NODES];
__device__ int   g_cursor[N_NODES];
__device__ int   g_bsum [NB1];
__device__ int   g_csr  [N_EDGES];                    // src ids grouped by dst
__device__ float g_M1p[4 * NF * NC];                  // K-split partials, [f][c]
__device__ float g_M2p[4 * NF * NC];

// ---------------------------------------------------------------------------
__global__ void k_init() {
    int i = blockIdx.x * blockDim.x + threadIdx.x;
    if (i < N_NODES) g_deg[i] = 0;
}

__global__ void k_deg(const int* __restrict__ dst) {
    int e = blockIdx.x * blockDim.x + threadIdx.x;
    if (e < N_EDGES) atomicAdd(&g_deg[dst[e]], 1);
}

// Level-1 scan: per-1024-block exclusive scan of g_deg -> g_off, block sums -> g_bsum
__global__ void k_scan1() {
    __shared__ int sh[SCAN_B];
    int i = blockIdx.x * SCAN_B + threadIdx.x;
    int v = (i < N_NODES) ? g_deg[i] : 0;
    sh[threadIdx.x] = v;
    __syncthreads();
    for (int off = 1; off < SCAN_B; off <<= 1) {
        int t = (threadIdx.x >= off) ? sh[threadIdx.x - off] : 0;
        __syncthreads();
        sh[threadIdx.x] += t;
        __syncthreads();
    }
    if (i < N_NODES) g_off[i] = sh[threadIdx.x] - v;      // exclusive, block-local
    if (threadIdx.x == SCAN_B - 1) g_bsum[blockIdx.x] = sh[SCAN_B - 1];
}

// Level-2 carry folded in: each 256-node block (aligned within one 1024-scan-block)
// sums the preceding g_bsum entries itself. Also finalizes cursors + norms.
__global__ void k_scan3() {
    __shared__ int carry_sh;
    if (threadIdx.x == 0) {
        int sb = (blockIdx.x * 256) >> 10;    // same for all 256 nodes (aligned)
        int c = 0;
#pragma unroll 8
        for (int j = 0; j < sb; j++) c += g_bsum[j];
        carry_sh = c;
    }
    __syncthreads();
    int i = blockIdx.x * 256 + threadIdx.x;
    if (i >= N_NODES) return;
    int off = g_off[i] + carry_sh;
    g_off[i] = off;
    g_cursor[i] = off;
    int d = g_deg[i];
    g_norm[i] = (d > 0) ? rsqrtf((float)d) : 1.0f;
}

__global__ void k_fill(const int* __restrict__ src, const int* __restrict__ dst) {
    int e = blockIdx.x * blockDim.x + threadIdx.x;
    if (e >= N_EDGES) return;
    int d = dst[e];
    int pos = atomicAdd(&g_cursor[d], 1);
    g_csr[pos] = src[e];
}

// Folded projection weights, K-split 4x for latency hiding.
// M1[c,f] = sum_h Wp[c,h]     * W_lin[h,f]
// M2[c,f] = sum_h Wp[c,128+h] * W_sgc[h,f]
__global__ void k_weights(const float* __restrict__ Wp,
                          const float* __restrict__ Wsgc,
                          const float* __restrict__ Wlin) {
    int c    = blockIdx.x;        // 0..39
    int sel  = blockIdx.y;        // 0 -> M1, 1 -> M2
    int part = blockIdx.z;        // 0..3, 32 h each
    int f    = threadIdx.x;       // 0..95
    const float* wp = Wp + c * 256 + sel * 128 + part * 32;
    const float* W  = (sel ? Wsgc : Wlin) + part * 32 * NF;
    float acc = 0.0f;
#pragma unroll
    for (int h = 0; h < 32; h++)
        acc = fmaf(__ldg(wp + h), __ldg(W + h * NF + f), acc);
    (sel ? g_M2p : g_M1p)[part * (NF * NC) + f * NC + c] = acc;
}

__device__ __forceinline__ void fma4(float4& a, float s, const float4 m) {
    a.x = fmaf(s, m.x, a.x);
    a.y = fmaf(s, m.y, a.y);
    a.z = fmaf(s, m.z, a.z);
    a.w = fmaf(s, m.w, a.w);
}
__device__ __forceinline__ void add4(float4& a, const float4 b) {
    a.x += b.x; a.y += b.y; a.z += b.z; a.w += b.w;
}

// Fused dual GEMM, 4 rows x 4 cols x 2 matrices per thread (LDS-traffic optimized):
//   out[v,:] = feat[v,:] @ M1^T            (base term, straight to d_out)
//   g_t[v,:] = norm[v] * (feat[v,:]@M2^T)  (pre-scaled propagation input)
// Dynamic smem: sM1 3840 + sM2 3840 + sF 64*97 floats = 55552 bytes.
__global__ void __launch_bounds__(160) k_gemm(const float* __restrict__ feat,
                                              float* __restrict__ out) {
    extern __shared__ float sh[];
    float* sM1 = sh;                    // [NF*NC]
    float* sM2 = sh + NF * NC;          // [NF*NC]
    float* sF  = sh + 2 * NF * NC;      // [GROWS*97]

    const int tid = threadIdx.y * 10 + threadIdx.x;
    for (int i = tid; i < NF * NC; i += 160) {
        sM1[i] = g_M1p[i] + g_M1p[i + 3840] + g_M1p[i + 7680] + g_M1p[i + 11520];
        sM2[i] = g_M2p[i] + g_M2p[i + 3840] + g_M2p[i + 7680] + g_M2p[i + 11520];
    }

    const int row0 = blockIdx.x * GROWS;
    for (int i = tid; i < GROWS * NF; i += 160) {
        int r = i / NF, f = i - r * NF;
        int v = row0 + r;
        sF[r * 97 + f] = (v < N_NODES) ? feat[(size_t)v * NF + f] : 0.0f;
    }
    __syncthreads();

    const int cx = threadIdx.x;            // col group: 4*cx .. 4*cx+3
    const int r0 = threadIdx.y * 4;        // rows r0 .. r0+3

    float4 a1[4], a2[4];
#pragma unroll
    for (int r = 0; r < 4; r++) { a1[r] = make_float4(0, 0, 0, 0); a2[r] = a1[r]; }

#pragma unroll 4
    for (int f = 0; f < NF; f++) {
        const float4 m1 = *reinterpret_cast<const float4*>(sM1 + f * NC + cx * 4);
        const float4 m2 = *reinterpret_cast<const float4*>(sM2 + f * NC + cx * 4);
#pragma unroll
        for (int r = 0; r < 4; r++) {
            const float fv = sF[(r0 + r) * 97 + f];
            fma4(a1[r], fv, m1);
            fma4(a2[r], fv, m2);
        }
    }

#pragma unroll
    for (int r = 0; r < 4; r++) {
        const int v = row0 + r0 + r;
        if (v < N_NODES) {
            float n = g_norm[v];
            *reinterpret_cast<float4*>(out + (size_t)v * NC + cx * 4) = a1[r];
            float4 t = a2[r]; t.x *= n; t.y *= n; t.z *= n; t.w *= n;
            *reinterpret_cast<float4*>(g_t + (size_t)v * NC + cx * 4) = t;
        }
    }
}

// Hop 1 (CSR gather, chunk-parallel): 10 lanes per node, one float4 each.
// Per edge, the 10-lane group loads one contiguous 160B source row (coalesced);
// the csr index load is a same-address broadcast. Output store fully coalesced.
// g_acc[v,:] = n[v]^2 * sum_{s in in(v)} g_t[s,:]
__global__ void k_gather1() {
    int t = blockIdx.x * blockDim.x + threadIdx.x;
    if (t >= N_NODES * 10) return;
    int v = t / 10;
    int c = t - v * 10;
    int beg = __ldg(&g_off[v]);
    int deg = __ldg(&g_deg[v]);
    const int* cp = g_csr + beg;
    float4 a = make_float4(0, 0, 0, 0);
#pragma unroll 4
    for (int i = 0; i < deg; i++) {
        int s = __ldg(cp + i);
        add4(a, *reinterpret_cast<const float4*>(g_t + (size_t)s * NC + c * 4));
    }
    float n = __ldg(&g_norm[v]);
    float s2 = n * n;
    a.x *= s2; a.y *= s2; a.z *= s2; a.w *= s2;
    reinterpret_cast<float4*>(g_acc)[t] = a;
}

// Hop 2 + epilogue: out[v,:] += n[v] * sum_{s in in(v)} g_acc[s,:]
__global__ void k_gather2(float* __restrict__ out) {
    int t = blockIdx.x * blockDim.x + threadIdx.x;
    if (t >= N_NODES * 10) return;
    int v = t / 10;
    int c = t - v * 10;
    int beg = __ldg(&g_off[v]);
    int deg = __ldg(&g_deg[v]);
    const int* cp = g_csr + beg;
    float4 a = make_float4(0, 0, 0, 0);
#pragma unroll 4
    for (int i = 0; i < deg; i++) {
        int s = __ldg(cp + i);
        add4(a, *reinterpret_cast<const float4*>(g_acc + (size_t)s * NC + c * 4));
    }
    float n = __ldg(&g_norm[v]);
    float4* po = reinterpret_cast<float4*>(out) + t;
    float4 b = *po;
    b.x = fmaf(n, a.x, b.x);
    b.y = fmaf(n, a.y, b.y);
    b.z = fmaf(n, a.z, b.z);
    b.w = fmaf(n, a.w, b.w);
    *po = b;
}

// ---------------------------------------------------------------------------
extern "C" void kernel_launch(void* const* d_in, const int* in_sizes, int n_in,
                              void* d_out, int out_size) {
    const float* feat  = (const float*)d_in[0];   // [50000, 96]
    const int*   src   = (const int*)  d_in[1];   // [800000]
    const int*   dst   = (const int*)  d_in[2];   // [800000]
    const float* Wsgc  = (const float*)d_in[3];   // [128, 96]
    const float* Wlin  = (const float*)d_in[4];   // [128, 96]
    const float* Wproj = (const float*)d_in[5];   // [40, 256]
    float* out = (float*)d_out;                   // [50000, 40]

    const int gemm_smem = (2 * NF * NC + GROWS * 97) * (int)sizeof(float); // 55552
    cudaFuncSetAttribute(k_gemm, cudaFuncAttributeMaxDynamicSharedMemorySize, gemm_smem);

    k_init<<<(N_NODES + 255) / 256, 256>>>();
    k_deg <<<(N_EDGES + 255) / 256, 256>>>(dst);
    k_scan1<<<NB1, SCAN_B>>>();
    k_scan3<<<(N_NODES + 255) / 256, 256>>>();
    k_fill<<<(N_EDGES + 255) / 256, 256>>>(src, dst);
    k_weights<<<dim3(NC, 2, 4), NF>>>(Wproj, Wsgc, Wlin);
    k_gemm<<<(N_NODES + GROWS - 1) / GROWS, dim3(10, 16), gemm_smem>>>(feat, out);
    k_gather1<<<(N_NODES * 10 + 255) / 256, 256>>>();
    k_gather2<<<(N_NODES * 10 + 255) / 256, 256>>>(out);
}

// round 13
// speedup vs baseline: 1.4926x; 1.0166x over previous
#include <cuda_runtime.h>
#include <math.h>
#include <stdint.h>

#define N_NODES   50000
#define N_EDGES   800000
#define NF        96
#define NH        128
#define NC        40
#define GROWS     64                    // rows per GEMM block
#define SCAN_B    1024
#define NB1       ((N_NODES + SCAN_B - 1) / SCAN_B)   // 49

// ---------------- device scratch (static, allocation-free) ----------------
// Symbols referenced ONLY from device code (host-side use gives shadow addr).
__device__ __align__(16) float g_t   [N_NODES * NC];  // norm*feat@M2^T, prop state
__device__ __align__(16) float g_acc [N_NODES * NC];  // hop-1 result
__device__ float g_norm[N_NODES];
__device__ int   g_deg  [N_NODES];
__device__ int   g_off  [N_NODES];
__device__ int   g_cursor[N_NODES];
__device__ int   g_bsum [NB1];
__device__ int   g_csr  [N_EDGES];                    // src ids grouped by dst
__device__ float g_M1p[4 * NF * NC];                  // K-split partials, [f][c]
__device__ float g_M2p[4 * NF * NC];

// ---------------------------------------------------------------------------
__global__ void k_init() {
    int i = blockIdx.x * blockDim.x + threadIdx.x;
    if (i < N_NODES) g_deg[i] = 0;
}

__global__ void k_deg(const int* __restrict__ dst) {
    int e = blockIdx.x * blockDim.x + threadIdx.x;
    if (e < N_EDGES) atomicAdd(&g_deg[dst[e]], 1);
}

// Level-1 scan: per-1024-block exclusive scan of g_deg -> g_off, block sums -> g_bsum
__global__ void k_scan1() {
    __shared__ int sh[SCAN_B];
    int i = blockIdx.x * SCAN_B + threadIdx.x;
    int v = (i < N_NODES) ? g_deg[i] : 0;
    sh[threadIdx.x] = v;
    __syncthreads();
    for (int off = 1; off < SCAN_B; off <<= 1) {
        int t = (threadIdx.x >= off) ? sh[threadIdx.x - off] : 0;
        __syncthreads();
        sh[threadIdx.x] += t;
        __syncthreads();
    }
    if (i < N_NODES) g_off[i] = sh[threadIdx.x] - v;      // exclusive, block-local
    if (threadIdx.x == SCAN_B - 1) g_bsum[blockIdx.x] = sh[SCAN_B - 1];
}

// Level-2 carry folded in: each 256-node block (aligned within one 1024-scan-block)
// sums the preceding g_bsum entries itself. Also finalizes cursors + norms.
__global__ void k_scan3() {
    __shared__ int carry_sh;
    if (threadIdx.x == 0) {
        int sb = (blockIdx.x * 256) >> 10;    // same for all 256 nodes (aligned)
        int c = 0;
#pragma unroll 8
        for (int j = 0; j < sb; j++) c += g_bsum[j];
        carry_sh = c;
    }
    __syncthreads();
    int i = blockIdx.x * 256 + threadIdx.x;
    if (i >= N_NODES) return;
    int off = g_off[i] + carry_sh;
    g_off[i] = off;
    g_cursor[i] = off;
    int d = g_deg[i];
    g_norm[i] = (d > 0) ? rsqrtf((float)d) : 1.0f;
}

__global__ void k_fill(const int* __restrict__ src, const int* __restrict__ dst) {
    int e = blockIdx.x * blockDim.x + threadIdx.x;
    if (e >= N_EDGES) return;
    int d = dst[e];
    int pos = atomicAdd(&g_cursor[d], 1);
    g_csr[pos] = src[e];
}

// Folded projection weights, K-split 4x for latency hiding.
// M1[c,f] = sum_h Wp[c,h]     * W_lin[h,f]
// M2[c,f] = sum_h Wp[c,128+h] * W_sgc[h,f]
__global__ void k_weights(const float* __restrict__ Wp,
                          const float* __restrict__ Wsgc,
                          const float* __restrict__ Wlin) {
    int c    = blockIdx.x;        // 0..39
    int sel  = blockIdx.y;        // 0 -> M1, 1 -> M2
    int part = blockIdx.z;        // 0..3, 32 h each
    int f    = threadIdx.x;       // 0..95
    const float* wp = Wp + c * 256 + sel * 128 + part * 32;
    const float* W  = (sel ? Wsgc : Wlin) + part * 32 * NF;
    float acc = 0.0f;
#pragma unroll
    for (int h = 0; h < 32; h++)
        acc = fmaf(__ldg(wp + h), __ldg(W + h * NF + f), acc);
    (sel ? g_M2p : g_M1p)[part * (NF * NC) + f * NC + c] = acc;
}

__device__ __forceinline__ void fma4(float4& a, float s, const float4 m) {
    a.x = fmaf(s, m.x, a.x);
    a.y = fmaf(s, m.y, a.y);
    a.z = fmaf(s, m.z, a.z);
    a.w = fmaf(s, m.w, a.w);
}
__device__ __forceinline__ void add4(float4& a, const float4 b) {
    a.x += b.x; a.y += b.y; a.z += b.z; a.w += b.w;
}

// Fused dual GEMM, 4 rows x 4 cols x 2 matrices per thread (LDS-traffic optimized):
//   out[v,:] = feat[v,:] @ M1^T            (base term, straight to d_out)
//   g_t[v,:] = norm[v] * (feat[v,:]@M2^T)  (pre-scaled propagation input)
// Dynamic smem: sM1 3840 + sM2 3840 + sF 64*97 floats = 55552 bytes.
__global__ void __launch_bounds__(160) k_gemm(const float* __restrict__ feat,
                                              float* __restrict__ out) {
    extern __shared__ float sh[];
    float* sM1 = sh;                    // [NF*NC]
    float* sM2 = sh + NF * NC;          // [NF*NC]
    float* sF  = sh + 2 * NF * NC;      // [GROWS*97]

    const int tid = threadIdx.y * 10 + threadIdx.x;
    for (int i = tid; i < NF * NC; i += 160) {
        sM1[i] = g_M1p[i] + g_M1p[i + 3840] + g_M1p[i + 7680] + g_M1p[i + 11520];
        sM2[i] = g_M2p[i] + g_M2p[i + 3840] + g_M2p[i + 7680] + g_M2p[i + 11520];
    }

    const int row0 = blockIdx.x * GROWS;
    for (int i = tid; i < GROWS * NF; i += 160) {
        int r = i / NF, f = i - r * NF;
        int v = row0 + r;
        sF[r * 97 + f] = (v < N_NODES) ? feat[(size_t)v * NF + f] : 0.0f;
    }
    __syncthreads();

    const int cx = threadIdx.x;            // col group: 4*cx .. 4*cx+3
    const int r0 = threadIdx.y * 4;        // rows r0 .. r0+3

    float4 a1[4], a2[4];
#pragma unroll
    for (int r = 0; r < 4; r++) { a1[r] = make_float4(0, 0, 0, 0); a2[r] = a1[r]; }

#pragma unroll 4
    for (int f = 0; f < NF; f++) {
        const float4 m1 = *reinterpret_cast<const float4*>(sM1 + f * NC + cx * 4);
        const float4 m2 = *reinterpret_cast<const float4*>(sM2 + f * NC + cx * 4);
#pragma unroll
        for (int r = 0; r < 4; r++) {
            const float fv = sF[(r0 + r) * 97 + f];
            fma4(a1[r], fv, m1);
            fma4(a2[r], fv, m2);
        }
    }

#pragma unroll
    for (int r = 0; r < 4; r++) {
        const int v = row0 + r0 + r;
        if (v < N_NODES) {
            float n = g_norm[v];
            *reinterpret_cast<float4*>(out + (size_t)v * NC + cx * 4) = a1[r];
            float4 t = a2[r]; t.x *= n; t.y *= n; t.z *= n; t.w *= n;
            *reinterpret_cast<float4*>(g_t + (size_t)v * NC + cx * 4) = t;
        }
    }
}

// Hop 1 (CSR gather, chunk-parallel): 10 lanes per node, one float4 each.
// Per edge, the 10-lane group loads one contiguous 160B source row (coalesced);
// the csr index load is a same-address broadcast. Output store fully coalesced.
// g_acc[v,:] = n[v]^2 * sum_{s in in(v)} g_t[s,:]
__global__ void k_gather1() {
    int t = blockIdx.x * blockDim.x + threadIdx.x;
    if (t >= N_NODES * 10) return;
    int v = t / 10;
    int c = t - v * 10;
    int beg = __ldg(&g_off[v]);
    int deg = __ldg(&g_deg[v]);
    const int* cp = g_csr + beg;
    float4 a = make_float4(0, 0, 0, 0);
#pragma unroll 4
    for (int i = 0; i < deg; i++) {
        int s = __ldg(cp + i);
        add4(a, *reinterpret_cast<const float4*>(g_t + (size_t)s * NC + c * 4));
    }
    float n = __ldg(&g_norm[v]);
    float s2 = n * n;
    a.x *= s2; a.y *= s2; a.z *= s2; a.w *= s2;
    reinterpret_cast<float4*>(g_acc)[t] = a;
}

// Hop 2 + epilogue: out[v,:] += n[v] * sum_{s in in(v)} g_acc[s,:]
__global__ void k_gather2(float* __restrict__ out) {
    int t = blockIdx.x * blockDim.x + threadIdx.x;
    if (t >= N_NODES * 10) return;
    int v = t / 10;
    int c = t - v * 10;
    int beg = __ldg(&g_off[v]);
    int deg = __ldg(&g_deg[v]);
    const int* cp = g_csr + beg;
    float4 a = make_float4(0, 0, 0, 0);
#pragma unroll 4
    for (int i = 0; i < deg; i++) {
        int s = __ldg(cp + i);
        add4(a, *reinterpret_cast<const float4*>(g_acc + (size_t)s * NC + c * 4));
    }
    float n = __ldg(&g_norm[v]);
    float4* po = reinterpret_cast<float4*>(out) + t;
    float4 b = *po;
    b.x = fmaf(n, a.x, b.x);
    b.y = fmaf(n, a.y, b.y);
    b.z = fmaf(n, a.z, b.z);
    b.w = fmaf(n, a.w, b.w);
    *po = b;
}

// ---------------------------------------------------------------------------
extern "C" void kernel_launch(void* const* d_in, const int* in_sizes, int n_in,
                              void* d_out, int out_size) {
    const float* feat  = (const float*)d_in[0];   // [50000, 96]
    const int*   src   = (const int*)  d_in[1];   // [800000]
    const int*   dst   = (const int*)  d_in[2];   // [800000]
    const float* Wsgc  = (const float*)d_in[3];   // [128, 96]
    const float* Wlin  = (const float*)d_in[4];   // [128, 96]
    const float* Wproj = (const float*)d_in[5];   // [40, 256]
    float* out = (float*)d_out;                   // [50000, 40]

    const int gemm_smem = (2 * NF * NC + GROWS * 97) * (int)sizeof(float); // 55552
    cudaFuncSetAttribute(k_gemm, cudaFuncAttributeMaxDynamicSharedMemorySize, gemm_smem);

    k_init<<<(N_NODES + 255) / 256, 256>>>();
    k_deg <<<(N_EDGES + 255) / 256, 256>>>(dst);
    k_scan1<<<NB1, SCAN_B>>>();
    k_scan3<<<(N_NODES + 255) / 256, 256>>>();
    k_fill<<<(N_EDGES + 255) / 256, 256>>>(src, dst);
    k_weights<<<dim3(NC, 2, 4), NF>>>(Wproj, Wsgc, Wlin);
    k_gemm<<<(N_NODES + GROWS - 1) / GROWS, dim3(10, 16), gemm_smem>>>(feat, out);
    k_gather1<<<(N_NODES * 10 + 255) / 256, 256>>>();
    k_gather2<<<(N_NODES * 10 + 255) / 256, 256>>>(out);
}